// round 16
// baseline (speedup 1.0000x reference)
#include <cuda_runtime.h>
#include <cuda_fp16.h>
#include <cstdint>
#include <math.h>

// ---------------- problem constants ----------------
#define T_TOKENS 4096
#define DDIM     1024
#define NEXP     8
#define MDIM     1408
#define BM       128
#define BN       64
#define BN2      128
#define PAIRS_PAD 9216
#define NTILES   (PAIRS_PAD / BM)     // 72
#define G1_CH    (DDIM / 32)          // 32
#define G2_CH    (MDIM / 32)          // 44

// ---------------- device scratch (BSS zero-init; counters recycled per call) ----------------
__device__ __half g_Hf[(size_t)PAIRS_PAD * MDIM];
__device__ float g_Od[(size_t)PAIRS_PAD * DDIM];
__device__ int   g_pair_tok[PAIRS_PAD];
__device__ int   g_tok_pos[T_TOKENS * 2];
__device__ int   g_cnt[NEXP];
__device__ int   g_fill[NEXP];
__device__ int   g_segs[NEXP + 1];
__device__ int   g_tok_e[T_TOKENS * 2];
__device__ float g_tok_p[T_TOKENS * 2];

// ---------------- helpers ----------------
__device__ __forceinline__ uint32_t smem_u32(const void* p) {
    uint32_t a;
    asm("{ .reg .u64 t; cvta.to.shared.u64 t, %1; cvt.u32.u64 %0, t; }" : "=r"(a) : "l"(p));
    return a;
}
__device__ __forceinline__ void ldsm_x4(uint32_t* r, uint32_t addr) {
    asm volatile("ldmatrix.sync.aligned.m8n8.x4.shared.b16 {%0,%1,%2,%3}, [%4];"
        : "=r"(r[0]), "=r"(r[1]), "=r"(r[2]), "=r"(r[3]) : "r"(addr));
}
__device__ __forceinline__ void ldsm_x4_t(uint32_t* r, uint32_t addr) {
    asm volatile("ldmatrix.sync.aligned.m8n8.x4.trans.shared.b16 {%0,%1,%2,%3}, [%4];"
        : "=r"(r[0]), "=r"(r[1]), "=r"(r[2]), "=r"(r[3]) : "r"(addr));
}
__device__ __forceinline__ void mma16816(float* d, const uint32_t* a, const uint32_t* b) {
    asm volatile("mma.sync.aligned.m16n8k16.row.col.f32.f16.f16.f32 "
        "{%0,%1,%2,%3},{%4,%5,%6,%7},{%8,%9},{%0,%1,%2,%3};"
        : "+f"(d[0]), "+f"(d[1]), "+f"(d[2]), "+f"(d[3])
        : "r"(a[0]), "r"(a[1]), "r"(a[2]), "r"(a[3]), "r"(b[0]), "r"(b[1]));
}
__device__ __forceinline__ uint2 cvt4(float4 v) {
    __half2 a = __floats2half2_rn(v.x, v.y);
    __half2 b = __floats2half2_rn(v.z, v.w);
    return make_uint2(*(uint32_t*)&a, *(uint32_t*)&b);
}

// ---------------- router: 1 warp/token ----------------
__global__ void router_kernel(const float* __restrict__ x, const float* __restrict__ wg) {
    int warp = (blockIdx.x * blockDim.x + threadIdx.x) >> 5;
    int lane = threadIdx.x & 31;
    if (warp >= T_TOKENS) return;
    const float* xr = x + (size_t)warp * DDIM;
    float acc[NEXP];
#pragma unroll
    for (int e = 0; e < NEXP; e++) acc[e] = 0.0f;
    for (int d = lane; d < DDIM; d += 32) {
        float xv = xr[d];
        const float4* wr = (const float4*)(wg + (size_t)d * NEXP);
        float4 w0 = wr[0], w1 = wr[1];
        acc[0] += xv * w0.x; acc[1] += xv * w0.y;
        acc[2] += xv * w0.z; acc[3] += xv * w0.w;
        acc[4] += xv * w1.x; acc[5] += xv * w1.y;
        acc[6] += xv * w1.z; acc[7] += xv * w1.w;
    }
#pragma unroll
    for (int off = 16; off; off >>= 1)
#pragma unroll
        for (int e = 0; e < NEXP; e++)
            acc[e] += __shfl_xor_sync(0xffffffffu, acc[e], off);
    if (lane == 0) {
        int i0 = 0;
#pragma unroll
        for (int e = 1; e < NEXP; e++) if (acc[e] > acc[i0]) i0 = e;
        int i1 = (i0 == 0) ? 1 : 0;
#pragma unroll
        for (int e = 0; e < NEXP; e++)
            if (e != i0 && acc[e] > acc[i1]) i1 = e;
        float p1 = expf(acc[i1] - acc[i0]);
        float z = 1.0f + p1;
        g_tok_e[warp * 2 + 0] = i0; g_tok_p[warp * 2 + 0] = 1.0f / z;
        g_tok_e[warp * 2 + 1] = i1; g_tok_p[warp * 2 + 1] = p1 / z;
        atomicAdd(&g_cnt[i0], 1);
        atomicAdd(&g_cnt[i1], 1);
    }
}

// ---------------- scatter (fused scan) ----------------
__global__ void scatter_kernel() {
    int t = blockIdx.x * blockDim.x + threadIdx.x;
    if (t >= T_TOKENS) return;
    int segs[NEXP + 1];
    {
        int tot = 0;
#pragma unroll
        for (int e = 0; e < NEXP; e++) {
            segs[e] = tot;
            tot += ((g_cnt[e] + BM - 1) / BM) * BM;
        }
        segs[NEXP] = tot;
    }
    if (t == 0) {
#pragma unroll
        for (int e = 0; e <= NEXP; e++) g_segs[e] = segs[e];
    }
#pragma unroll
    for (int k = 0; k < 2; k++) {
        int e = g_tok_e[t * 2 + k];
        int pos = segs[e] + atomicAdd(&g_fill[e], 1);
        g_pair_tok[pos] = t;
        g_tok_pos[t * 2 + k] = pos;
    }
}

// ---------------- combine + counter recycle ----------------
__global__ void combine_kernel(float4* __restrict__ out4) {
    int i = blockIdx.x * blockDim.x + threadIdx.x;
    int t = i >> 8;
    int c4 = i & 255;
    int pos0 = g_tok_pos[t * 2], pos1 = g_tok_pos[t * 2 + 1];
    float p0 = g_tok_p[t * 2], p1 = g_tok_p[t * 2 + 1];
    const float4* O = (const float4*)g_Od;
    float4 a = O[(size_t)pos0 * 256 + c4];
    float4 b = O[(size_t)pos1 * 256 + c4];
    out4[i] = make_float4(p0 * a.x + p1 * b.x, p0 * a.y + p1 * b.y,
                          p0 * a.z + p1 * b.z, p0 * a.w + p1 * b.w);
    if (blockIdx.x == 0 && threadIdx.x < NEXP) {
        g_cnt[threadIdx.x] = 0;
        g_fill[threadIdx.x] = 0;
    }
}

// ---------------- GEMM1: R8 shape, fp16 staging regs, 2 CTA/SM ----------------
#define S1_A    0
#define S1_BG   10240
#define S1_BU   14848
#define S1_TOK  19456
#define S1_SE   19968
#define S1_SIZE 19984

__global__ __launch_bounds__(256, 2) void gemm1_kernel(const float* __restrict__ x,
                                                       const float* __restrict__ w_g,
                                                       const float* __restrict__ w_u) {
    __shared__ __align__(128) char sm[S1_SIZE];
    const uint32_t sb = smem_u32(sm);
    const int tid = threadIdx.x;
    const int lane = tid & 31, warp = tid >> 5;
    const int wm = warp >> 1, wn = warp & 1;
    const int p0 = blockIdx.x * BM;
    const int m0 = blockIdx.y * BN;

    if (tid == 0) {
        int e = -1;
        if (p0 < g_segs[NEXP]) { e = 0; while (p0 >= g_segs[e + 1]) e++; }
        *(int*)(sm + S1_SE) = e;
    }
    int* tokp = (int*)(sm + S1_TOK);
    if (tid < BM) tokp[tid] = g_pair_tok[p0 + tid];
    __syncthreads();
    const int e = *(int*)(sm + S1_SE);
    if (e < 0) return;

    const float* Wg = w_g + (size_t)e * DDIM * MDIM;
    const float* Wu = w_u + (size_t)e * DDIM * MDIM;

    const int a_row = tid >> 3, a_kq = (tid & 7) * 4;
    const int b_k = tid >> 4, b_nq = (tid & 15) * 4;
    const int tokA0 = tokp[a_row] & 0xFFF, tokA1 = tokp[a_row + 32] & 0xFFF,
              tokA2 = tokp[a_row + 64] & 0xFFF, tokA3 = tokp[a_row + 96] & 0xFFF;

    float accG[2][4][4], accU[2][4][4];
#pragma unroll
    for (int i = 0; i < 2; i++)
#pragma unroll
        for (int j = 0; j < 4; j++)
#pragma unroll
            for (int q = 0; q < 4; q++) { accG[i][j][q] = 0.f; accU[i][j][q] = 0.f; }

    const int lm_off = ((lane >> 3) & 1) * 8 + (lane & 7);
    const int lm_hi  = (lane >> 4) * 8;
    const uint32_t aA0 = sb + S1_A + (wm * 32 + lm_off) * 80 + lm_hi * 2;
    const uint32_t bG0 = sb + S1_BG + lm_off * 144 + (wn * 32 + lm_hi) * 2;
    const uint32_t bU0 = sb + S1_BU + lm_off * 144 + (wn * 32 + lm_hi) * 2;

    // staging in fp16 (cvt at load) -> half the live registers across sync
    uint2 stA[4], stG[2], stU[2];
    {
        const int kk = 0;
        stA[0] = cvt4(*(const float4*)(x + (size_t)tokA0 * DDIM + kk + a_kq));
        stA[1] = cvt4(*(const float4*)(x + (size_t)tokA1 * DDIM + kk + a_kq));
        stA[2] = cvt4(*(const float4*)(x + (size_t)tokA2 * DDIM + kk + a_kq));
        stA[3] = cvt4(*(const float4*)(x + (size_t)tokA3 * DDIM + kk + a_kq));
        stG[0] = cvt4(*(const float4*)(Wg + (size_t)(kk + b_k) * MDIM + m0 + b_nq));
        stG[1] = cvt4(*(const float4*)(Wg + (size_t)(kk + b_k + 16) * MDIM + m0 + b_nq));
        stU[0] = cvt4(*(const float4*)(Wu + (size_t)(kk + b_k) * MDIM + m0 + b_nq));
        stU[1] = cvt4(*(const float4*)(Wu + (size_t)(kk + b_k + 16) * MDIM + m0 + b_nq));
    }

    for (int ch = 0; ch < G1_CH; ch++) {
#pragma unroll
        for (int i = 0; i < 4; i++)
            *(uint2*)(sm + S1_A + (a_row + i * 32) * 80 + a_kq * 2) = stA[i];
#pragma unroll
        for (int i = 0; i < 2; i++) {
            uint32_t off = (b_k + i * 16) * 144 + b_nq * 2;
            *(uint2*)(sm + S1_BG + off) = stG[i];
            *(uint2*)(sm + S1_BU + off) = stU[i];
        }
        __syncthreads();
        if (ch + 1 < G1_CH) {
            const int kk = (ch + 1) * 32;
            stA[0] = cvt4(*(const float4*)(x + (size_t)tokA0 * DDIM + kk + a_kq));
            stA[1] = cvt4(*(const float4*)(x + (size_t)tokA1 * DDIM + kk + a_kq));
            stA[2] = cvt4(*(const float4*)(x + (size_t)tokA2 * DDIM + kk + a_kq));
            stA[3] = cvt4(*(const float4*)(x + (size_t)tokA3 * DDIM + kk + a_kq));
            stG[0] = cvt4(*(const float4*)(Wg + (size_t)(kk + b_k) * MDIM + m0 + b_nq));
            stG[1] = cvt4(*(const float4*)(Wg + (size_t)(kk + b_k + 16) * MDIM + m0 + b_nq));
            stU[0] = cvt4(*(const float4*)(Wu + (size_t)(kk + b_k) * MDIM + m0 + b_nq));
            stU[1] = cvt4(*(const float4*)(Wu + (size_t)(kk + b_k + 16) * MDIM + m0 + b_nq));
        }
#pragma unroll
        for (int kh = 0; kh < 2; kh++) {
            uint32_t A[8];
            ldsm_x4(A + 0, aA0 + kh * 32);
            ldsm_x4(A + 4, aA0 + 1280 + kh * 32);
            uint32_t Bg[8], Bu[8];
            ldsm_x4_t(Bg + 0, bG0 + kh * 2304);
            ldsm_x4_t(Bg + 4, bG0 + kh * 2304 + 32);
            ldsm_x4_t(Bu + 0, bU0 + kh * 2304);
            ldsm_x4_t(Bu + 4, bU0 + kh * 2304 + 32);
#pragma unroll
            for (int mi = 0; mi < 2; mi++)
#pragma unroll
                for (int nf = 0; nf < 4; nf++) {
                    const uint32_t* bg = &Bg[(nf >> 1) * 4 + (nf & 1) * 2];
                    const uint32_t* bu = &Bu[(nf >> 1) * 4 + (nf & 1) * 2];
                    mma16816(accG[mi][nf], &A[mi * 4], bg);
                    mma16816(accU[mi][nf], &A[mi * 4], bu);
                }
        }
        __syncthreads();
    }

    const int rg = lane >> 2, cg = (lane & 3) * 2;
#pragma unroll
    for (int mi = 0; mi < 2; mi++)
#pragma unroll
        for (int nf = 0; nf < 4; nf++) {
            const float* g = accG[mi][nf];
            const float* u = accU[mi][nf];
            int c = wn * 32 + nf * 8 + cg;
            size_t b0 = (size_t)(p0 + wm * 32 + mi * 16 + rg) * MDIM + m0 + c;
            size_t b1 = b0 + (size_t)8 * MDIM;
            float h0 = g[0] / (1.f + __expf(-g[0])) * u[0];
            float h1 = g[1] / (1.f + __expf(-g[1])) * u[1];
            float h2 = g[2] / (1.f + __expf(-g[2])) * u[2];
            float h3 = g[3] / (1.f + __expf(-g[3])) * u[3];
            *(__half2*)&g_Hf[b0] = __floats2half2_rn(h0, h1);
            *(__half2*)&g_Hf[b1] = __floats2half2_rn(h2, h3);
        }
}

// ---------------- GEMM2: R15 config, fp16 B staging regs ----------------
#define S2_A    0
#define S2_B    10240
#define S2_SE   18944
#define S2_SIZE 18960

__global__ __launch_bounds__(256) void gemm2_kernel(const float* __restrict__ w_d) {
    __shared__ __align__(128) char sm[S2_SIZE];
    const uint32_t sb = smem_u32(sm);
    const int tid = threadIdx.x;
    const int lane = tid & 31, warp = tid >> 5;
    const int wm = warp >> 2, wn = warp & 3;
    const int p0 = blockIdx.x * BM;
    const int d0 = blockIdx.y * BN2;

    if (tid == 0) {
        int e = -1;
        if (p0 < g_segs[NEXP]) { e = 0; while (p0 >= g_segs[e + 1]) e++; }
        *(int*)(sm + S2_SE) = e;
    }
    __syncthreads();
    const int e = *(int*)(sm + S2_SE);
    if (e < 0) return;

    const float* Wd = w_d + (size_t)e * MDIM * DDIM;

    const int a_row = tid >> 2, a_q = tid & 3;
    const int b_r = tid >> 5, b_q = tid & 31;

    float acc[4][4][4];
#pragma unroll
    for (int i = 0; i < 4; i++)
#pragma unroll
        for (int j = 0; j < 4; j++)
#pragma unroll
            for (int q = 0; q < 4; q++) acc[i][j][q] = 0.f;

    const int lm_off = ((lane >> 3) & 1) * 8 + (lane & 7);
    const int lm_hi  = (lane >> 4) * 8;
    const uint32_t aA0 = sb + S2_A + (wm * 64 + lm_off) * 80 + lm_hi * 2;
    const uint32_t bB0 = sb + S2_B + lm_off * 272 + (wn * 32 + lm_hi) * 2;

    uint4 stA[2];
    uint2 stB[4];
    {
        const int kk = 0;
#pragma unroll
        for (int i = 0; i < 2; i++)
            stA[i] = *(const uint4*)&g_Hf[(size_t)(p0 + a_row + i * 64) * MDIM + kk + a_q * 8];
#pragma unroll
        for (int i = 0; i < 4; i++)
            stB[i] = cvt4(*(const float4*)(Wd + (size_t)(kk + b_r + i * 8) * DDIM + d0 + b_q * 4));
    }

    for (int ch = 0; ch < G2_CH; ch++) {
#pragma unroll
        for (int i = 0; i < 2; i++)
            *(uint4*)(sm + S2_A + (a_row + i * 64) * 80 + a_q * 16) = stA[i];
#pragma unroll
        for (int i = 0; i < 4; i++)
            *(uint2*)(sm + S2_B + (b_r + i * 8) * 272 + b_q * 8) = stB[i];
        __syncthreads();
        if (ch + 1 < G2_CH) {
            const int kk = (ch + 1) * 32;
#pragma unroll
            for (int i = 0; i < 2; i++)
                stA[i] = *(const uint4*)&g_Hf[(size_t)(p0 + a_row + i * 64) * MDIM + kk + a_q * 8];
#pragma unroll
            for (int i = 0; i < 4; i++)
                stB[i] = cvt4(*(const float4*)(Wd + (size_t)(kk + b_r + i * 8) * DDIM + d0 + b_q * 4));
        }
#pragma unroll
        for (int kh = 0; kh < 2; kh++) {
            uint32_t A[16];
#pragma unroll
            for (int f = 0; f < 4; f++)
                ldsm_x4(A + f * 4, aA0 + f * 1280 + kh * 32);
            uint32_t B[8];
            ldsm_x4_t(B + 0, bB0 + kh * 4352);
            ldsm_x4_t(B + 4, bB0 + kh * 4352 + 32);
#pragma unroll
            for (int mi = 0; mi < 4; mi++)
#pragma unroll
                for (int nf = 0; nf < 4; nf++)
                    mma16816(acc[mi][nf], &A[mi * 4], &B[(nf >> 1) * 4 + (nf & 1) * 2]);
        }
        __syncthreads();
    }

    const int rg = lane >> 2, cg = (lane & 3) * 2;
#pragma unroll
    for (int mi = 0; mi < 4; mi++)
#pragma unroll
        for (int nf = 0; nf < 4; nf++) {
            const float* d = acc[mi][nf];
            int c = wn * 32 + nf * 8 + cg;
            int r0 = wm * 64 + mi * 16 + rg;
            size_t o0 = (size_t)(p0 + r0) * DDIM + d0 + c;
            size_t o1 = o0 + (size_t)8 * DDIM;
            *(float2*)&g_Od[o0] = make_float2(d[0], d[1]);
            *(float2*)&g_Od[o1] = make_float2(d[2], d[3]);
        }
}

// ---------------- launch ----------------
extern "C" void kernel_launch(void* const* d_in, const int* in_sizes, int n_in,
                              void* d_out, int out_size) {
    const float* x      = (const float*)d_in[0];
    const float* w_gate = (const float*)d_in[1];
    const float* w_g    = (const float*)d_in[2];
    const float* w_u    = (const float*)d_in[3];
    const float* w_d    = (const float*)d_in[4];
    float* out = (float*)d_out;

    router_kernel<<<(T_TOKENS * 32 + 255) / 256, 256>>>(x, w_gate);
    scatter_kernel<<<(T_TOKENS + 255) / 256, 256>>>();
    gemm1_kernel<<<dim3(NTILES, MDIM / BN), 256>>>(x, w_g, w_u);
    gemm2_kernel<<<dim3(NTILES, DDIM / BN2), 256>>>(w_d);
    combine_kernel<<<(T_TOKENS * DDIM / 4 + 255) / 256, 256>>>((float4*)out);
}

// round 17
// speedup vs baseline: 1.1648x; 1.1648x over previous
#include <cuda_runtime.h>
#include <cuda_fp16.h>
#include <cstdint>
#include <math.h>

// ---------------- problem constants ----------------
#define T_TOKENS 4096
#define DDIM     1024
#define NEXP     8
#define MDIM     1408
#define BM       128
#define BN       64
#define BN2      128
#define PAIRS_PAD 9216
#define NTILES   (PAIRS_PAD / BM)     // 72
#define G1_CH    (DDIM / 32)          // 32
#define G2_CH    (MDIM / 32)          // 44

// ---------------- device scratch (BSS zero-init; counters recycled per call) ----------------
__device__ __half g_Hf[(size_t)PAIRS_PAD * MDIM];
__device__ float g_Od[(size_t)PAIRS_PAD * DDIM];
__device__ int   g_pair_tok[PAIRS_PAD];
__device__ int   g_tok_pos[T_TOKENS * 2];
__device__ int   g_cnt[NEXP];
__device__ int   g_fill[NEXP];
__device__ int   g_segs[NEXP + 1];
__device__ int   g_tok_e[T_TOKENS * 2];
__device__ float g_tok_p[T_TOKENS * 2];

// ---------------- helpers ----------------
__device__ __forceinline__ uint32_t smem_u32(const void* p) {
    uint32_t a;
    asm("{ .reg .u64 t; cvta.to.shared.u64 t, %1; cvt.u32.u64 %0, t; }" : "=r"(a) : "l"(p));
    return a;
}
__device__ __forceinline__ void ldsm_x4(uint32_t* r, uint32_t addr) {
    asm volatile("ldmatrix.sync.aligned.m8n8.x4.shared.b16 {%0,%1,%2,%3}, [%4];"
        : "=r"(r[0]), "=r"(r[1]), "=r"(r[2]), "=r"(r[3]) : "r"(addr));
}
__device__ __forceinline__ void ldsm_x4_t(uint32_t* r, uint32_t addr) {
    asm volatile("ldmatrix.sync.aligned.m8n8.x4.trans.shared.b16 {%0,%1,%2,%3}, [%4];"
        : "=r"(r[0]), "=r"(r[1]), "=r"(r[2]), "=r"(r[3]) : "r"(addr));
}
__device__ __forceinline__ void mma16816(float* d, const uint32_t* a, const uint32_t* b) {
    asm volatile("mma.sync.aligned.m16n8k16.row.col.f32.f16.f16.f32 "
        "{%0,%1,%2,%3},{%4,%5,%6,%7},{%8,%9},{%0,%1,%2,%3};"
        : "+f"(d[0]), "+f"(d[1]), "+f"(d[2]), "+f"(d[3])
        : "r"(a[0]), "r"(a[1]), "r"(a[2]), "r"(a[3]), "r"(b[0]), "r"(b[1]));
}
__device__ __forceinline__ uint2 cvt4(float4 v) {
    __half2 a = __floats2half2_rn(v.x, v.y);
    __half2 b = __floats2half2_rn(v.z, v.w);
    return make_uint2(*(uint32_t*)&a, *(uint32_t*)&b);
}

// ---------------- router: 1 warp/token ----------------
__global__ void router_kernel(const float* __restrict__ x, const float* __restrict__ wg) {
    int warp = (blockIdx.x * blockDim.x + threadIdx.x) >> 5;
    int lane = threadIdx.x & 31;
    if (warp >= T_TOKENS) return;
    const float* xr = x + (size_t)warp * DDIM;
    float acc[NEXP];
#pragma unroll
    for (int e = 0; e < NEXP; e++) acc[e] = 0.0f;
    for (int d = lane; d < DDIM; d += 32) {
        float xv = xr[d];
        const float4* wr = (const float4*)(wg + (size_t)d * NEXP);
        float4 w0 = wr[0], w1 = wr[1];
        acc[0] += xv * w0.x; acc[1] += xv * w0.y;
        acc[2] += xv * w0.z; acc[3] += xv * w0.w;
        acc[4] += xv * w1.x; acc[5] += xv * w1.y;
        acc[6] += xv * w1.z; acc[7] += xv * w1.w;
    }
#pragma unroll
    for (int off = 16; off; off >>= 1)
#pragma unroll
        for (int e = 0; e < NEXP; e++)
            acc[e] += __shfl_xor_sync(0xffffffffu, acc[e], off);
    if (lane == 0) {
        int i0 = 0;
#pragma unroll
        for (int e = 1; e < NEXP; e++) if (acc[e] > acc[i0]) i0 = e;
        int i1 = (i0 == 0) ? 1 : 0;
#pragma unroll
        for (int e = 0; e < NEXP; e++)
            if (e != i0 && acc[e] > acc[i1]) i1 = e;
        float p1 = expf(acc[i1] - acc[i0]);
        float z = 1.0f + p1;
        g_tok_e[warp * 2 + 0] = i0; g_tok_p[warp * 2 + 0] = 1.0f / z;
        g_tok_e[warp * 2 + 1] = i1; g_tok_p[warp * 2 + 1] = p1 / z;
        atomicAdd(&g_cnt[i0], 1);
        atomicAdd(&g_cnt[i1], 1);
    }
}

// ---------------- scatter (fused scan) ----------------
__global__ void scatter_kernel() {
    int t = blockIdx.x * blockDim.x + threadIdx.x;
    if (t >= T_TOKENS) return;
    int segs[NEXP + 1];
    {
        int tot = 0;
#pragma unroll
        for (int e = 0; e < NEXP; e++) {
            segs[e] = tot;
            tot += ((g_cnt[e] + BM - 1) / BM) * BM;
        }
        segs[NEXP] = tot;
    }
    if (t == 0) {
#pragma unroll
        for (int e = 0; e <= NEXP; e++) g_segs[e] = segs[e];
    }
#pragma unroll
    for (int k = 0; k < 2; k++) {
        int e = g_tok_e[t * 2 + k];
        int pos = segs[e] + atomicAdd(&g_fill[e], 1);
        g_pair_tok[pos] = t;
        g_tok_pos[t * 2 + k] = pos;
    }
}

// ---------------- combine + counter recycle ----------------
__global__ void combine_kernel(float4* __restrict__ out4) {
    int i = blockIdx.x * blockDim.x + threadIdx.x;
    int t = i >> 8;
    int c4 = i & 255;
    int pos0 = g_tok_pos[t * 2], pos1 = g_tok_pos[t * 2 + 1];
    float p0 = g_tok_p[t * 2], p1 = g_tok_p[t * 2 + 1];
    const float4* O = (const float4*)g_Od;
    float4 a = O[(size_t)pos0 * 256 + c4];
    float4 b = O[(size_t)pos1 * 256 + c4];
    out4[i] = make_float4(p0 * a.x + p1 * b.x, p0 * a.y + p1 * b.y,
                          p0 * a.z + p1 * b.z, p0 * a.w + p1 * b.w);
    if (blockIdx.x == 0 && threadIdx.x < NEXP) {
        g_cnt[threadIdx.x] = 0;
        g_fill[threadIdx.x] = 0;
    }
}

// ---------------- GEMM1: R15 body, cvt at STS, forced 2 CTA/SM ----------------
#define S1_A    0
#define S1_BG   10240
#define S1_BU   14848
#define S1_TOK  19456
#define S1_SE   19968
#define S1_SIZE 19984

__global__ __launch_bounds__(256, 2) void gemm1_kernel(const float* __restrict__ x,
                                                       const float* __restrict__ w_g,
                                                       const float* __restrict__ w_u) {
    __shared__ __align__(128) char sm[S1_SIZE];
    const uint32_t sb = smem_u32(sm);
    const int tid = threadIdx.x;
    const int lane = tid & 31, warp = tid >> 5;
    const int wm = warp >> 1, wn = warp & 1;
    const int p0 = blockIdx.x * BM;
    const int m0 = blockIdx.y * BN;

    if (tid == 0) {
        int e = -1;
        if (p0 < g_segs[NEXP]) { e = 0; while (p0 >= g_segs[e + 1]) e++; }
        *(int*)(sm + S1_SE) = e;
    }
    int* tokp = (int*)(sm + S1_TOK);
    if (tid < BM) tokp[tid] = g_pair_tok[p0 + tid];
    __syncthreads();
    const int e = *(int*)(sm + S1_SE);
    if (e < 0) return;

    const float* Wg = w_g + (size_t)e * DDIM * MDIM;
    const float* Wu = w_u + (size_t)e * DDIM * MDIM;

    const int a_row = tid >> 3, a_kq = (tid & 7) * 4;
    const int b_k = tid >> 4, b_nq = (tid & 15) * 4;
    const int tokA0 = tokp[a_row] & 0xFFF, tokA1 = tokp[a_row + 32] & 0xFFF,
              tokA2 = tokp[a_row + 64] & 0xFFF, tokA3 = tokp[a_row + 96] & 0xFFF;

    float accG[2][4][4], accU[2][4][4];
#pragma unroll
    for (int i = 0; i < 2; i++)
#pragma unroll
        for (int j = 0; j < 4; j++)
#pragma unroll
            for (int q = 0; q < 4; q++) { accG[i][j][q] = 0.f; accU[i][j][q] = 0.f; }

    const int lm_off = ((lane >> 3) & 1) * 8 + (lane & 7);
    const int lm_hi  = (lane >> 4) * 8;
    const uint32_t aA0 = sb + S1_A + (wm * 32 + lm_off) * 80 + lm_hi * 2;
    const uint32_t bG0 = sb + S1_BG + lm_off * 144 + (wn * 32 + lm_hi) * 2;
    const uint32_t bU0 = sb + S1_BU + lm_off * 144 + (wn * 32 + lm_hi) * 2;

    float4 stA[4], stG[2], stU[2];
    {
        const int kk = 0;
        stA[0] = *(const float4*)(x + (size_t)tokA0 * DDIM + kk + a_kq);
        stA[1] = *(const float4*)(x + (size_t)tokA1 * DDIM + kk + a_kq);
        stA[2] = *(const float4*)(x + (size_t)tokA2 * DDIM + kk + a_kq);
        stA[3] = *(const float4*)(x + (size_t)tokA3 * DDIM + kk + a_kq);
        stG[0] = *(const float4*)(Wg + (size_t)(kk + b_k) * MDIM + m0 + b_nq);
        stG[1] = *(const float4*)(Wg + (size_t)(kk + b_k + 16) * MDIM + m0 + b_nq);
        stU[0] = *(const float4*)(Wu + (size_t)(kk + b_k) * MDIM + m0 + b_nq);
        stU[1] = *(const float4*)(Wu + (size_t)(kk + b_k + 16) * MDIM + m0 + b_nq);
    }

    for (int ch = 0; ch < G1_CH; ch++) {
#pragma unroll
        for (int i = 0; i < 4; i++)
            *(uint2*)(sm + S1_A + (a_row + i * 32) * 80 + a_kq * 2) = cvt4(stA[i]);
#pragma unroll
        for (int i = 0; i < 2; i++) {
            uint32_t off = (b_k + i * 16) * 144 + b_nq * 2;
            *(uint2*)(sm + S1_BG + off) = cvt4(stG[i]);
            *(uint2*)(sm + S1_BU + off) = cvt4(stU[i]);
        }
        __syncthreads();
        if (ch + 1 < G1_CH) {
            const int kk = (ch + 1) * 32;
            stA[0] = *(const float4*)(x + (size_t)tokA0 * DDIM + kk + a_kq);
            stA[1] = *(const float4*)(x + (size_t)tokA1 * DDIM + kk + a_kq);
            stA[2] = *(const float4*)(x + (size_t)tokA2 * DDIM + kk + a_kq);
            stA[3] = *(const float4*)(x + (size_t)tokA3 * DDIM + kk + a_kq);
            stG[0] = *(const float4*)(Wg + (size_t)(kk + b_k) * MDIM + m0 + b_nq);
            stG[1] = *(const float4*)(Wg + (size_t)(kk + b_k + 16) * MDIM + m0 + b_nq);
            stU[0] = *(const float4*)(Wu + (size_t)(kk + b_k) * MDIM + m0 + b_nq);
            stU[1] = *(const float4*)(Wu + (size_t)(kk + b_k + 16) * MDIM + m0 + b_nq);
        }
#pragma unroll
        for (int kh = 0; kh < 2; kh++) {
            uint32_t A[8];
            ldsm_x4(A + 0, aA0 + kh * 32);
            ldsm_x4(A + 4, aA0 + 1280 + kh * 32);
            uint32_t Bg[8], Bu[8];
            ldsm_x4_t(Bg + 0, bG0 + kh * 2304);
            ldsm_x4_t(Bg + 4, bG0 + kh * 2304 + 32);
            ldsm_x4_t(Bu + 0, bU0 + kh * 2304);
            ldsm_x4_t(Bu + 4, bU0 + kh * 2304 + 32);
#pragma unroll
            for (int mi = 0; mi < 2; mi++)
#pragma unroll
                for (int nf = 0; nf < 4; nf++) {
                    const uint32_t* bg = &Bg[(nf >> 1) * 4 + (nf & 1) * 2];
                    const uint32_t* bu = &Bu[(nf >> 1) * 4 + (nf & 1) * 2];
                    mma16816(accG[mi][nf], &A[mi * 4], bg);
                    mma16816(accU[mi][nf], &A[mi * 4], bu);
                }
        }
        __syncthreads();
    }

    const int rg = lane >> 2, cg = (lane & 3) * 2;
#pragma unroll
    for (int mi = 0; mi < 2; mi++)
#pragma unroll
        for (int nf = 0; nf < 4; nf++) {
            const float* g = accG[mi][nf];
            const float* u = accU[mi][nf];
            int c = wn * 32 + nf * 8 + cg;
            size_t b0 = (size_t)(p0 + wm * 32 + mi * 16 + rg) * MDIM + m0 + c;
            size_t b1 = b0 + (size_t)8 * MDIM;
            float h0 = g[0] / (1.f + __expf(-g[0])) * u[0];
            float h1 = g[1] / (1.f + __expf(-g[1])) * u[1];
            float h2 = g[2] / (1.f + __expf(-g[2])) * u[2];
            float h3 = g[3] / (1.f + __expf(-g[3])) * u[3];
            *(__half2*)&g_Hf[b0] = __floats2half2_rn(h0, h1);
            *(__half2*)&g_Hf[b1] = __floats2half2_rn(h2, h3);
        }
}

// ---------------- GEMM2: exact R15 config (cvt at STS) ----------------
#define S2_A    0
#define S2_B    10240
#define S2_SE   18944
#define S2_SIZE 18960

__global__ __launch_bounds__(256) void gemm2_kernel(const float* __restrict__ w_d) {
    __shared__ __align__(128) char sm[S2_SIZE];
    const uint32_t sb = smem_u32(sm);
    const int tid = threadIdx.x;
    const int lane = tid & 31, warp = tid >> 5;
    const int wm = warp >> 2, wn = warp & 3;
    const int p0 = blockIdx.x * BM;
    const int d0 = blockIdx.y * BN2;

    if (tid == 0) {
        int e = -1;
        if (p0 < g_segs[NEXP]) { e = 0; while (p0 >= g_segs[e + 1]) e++; }
        *(int*)(sm + S2_SE) = e;
    }
    __syncthreads();
    const int e = *(int*)(sm + S2_SE);
    if (e < 0) return;

    const float* Wd = w_d + (size_t)e * MDIM * DDIM;

    const int a_row = tid >> 2, a_q = tid & 3;
    const int b_r = tid >> 5, b_q = tid & 31;

    float acc[4][4][4];
#pragma unroll
    for (int i = 0; i < 4; i++)
#pragma unroll
        for (int j = 0; j < 4; j++)
#pragma unroll
            for (int q = 0; q < 4; q++) acc[i][j][q] = 0.f;

    const int lm_off = ((lane >> 3) & 1) * 8 + (lane & 7);
    const int lm_hi  = (lane >> 4) * 8;
    const uint32_t aA0 = sb + S2_A + (wm * 64 + lm_off) * 80 + lm_hi * 2;
    const uint32_t bB0 = sb + S2_B + lm_off * 272 + (wn * 32 + lm_hi) * 2;

    uint4 stA[2];
    float4 stB[4];
    {
        const int kk = 0;
#pragma unroll
        for (int i = 0; i < 2; i++)
            stA[i] = *(const uint4*)&g_Hf[(size_t)(p0 + a_row + i * 64) * MDIM + kk + a_q * 8];
#pragma unroll
        for (int i = 0; i < 4; i++)
            stB[i] = *(const float4*)(Wd + (size_t)(kk + b_r + i * 8) * DDIM + d0 + b_q * 4);
    }

    for (int ch = 0; ch < G2_CH; ch++) {
#pragma unroll
        for (int i = 0; i < 2; i++)
            *(uint4*)(sm + S2_A + (a_row + i * 64) * 80 + a_q * 16) = stA[i];
#pragma unroll
        for (int i = 0; i < 4; i++)
            *(uint2*)(sm + S2_B + (b_r + i * 8) * 272 + b_q * 8) = cvt4(stB[i]);
        __syncthreads();
        if (ch + 1 < G2_CH) {
            const int kk = (ch + 1) * 32;
#pragma unroll
            for (int i = 0; i < 2; i++)
                stA[i] = *(const uint4*)&g_Hf[(size_t)(p0 + a_row + i * 64) * MDIM + kk + a_q * 8];
#pragma unroll
            for (int i = 0; i < 4; i++)
                stB[i] = *(const float4*)(Wd + (size_t)(kk + b_r + i * 8) * DDIM + d0 + b_q * 4);
        }
#pragma unroll
        for (int kh = 0; kh < 2; kh++) {
            uint32_t A[16];
#pragma unroll
            for (int f = 0; f < 4; f++)
                ldsm_x4(A + f * 4, aA0 + f * 1280 + kh * 32);
            uint32_t B[8];
            ldsm_x4_t(B + 0, bB0 + kh * 4352);
            ldsm_x4_t(B + 4, bB0 + kh * 4352 + 32);
#pragma unroll
            for (int mi = 0; mi < 4; mi++)
#pragma unroll
                for (int nf = 0; nf < 4; nf++)
                    mma16816(acc[mi][nf], &A[mi * 4], &B[(nf >> 1) * 4 + (nf & 1) * 2]);
        }
        __syncthreads();
    }

    const int rg = lane >> 2, cg = (lane & 3) * 2;
#pragma unroll
    for (int mi = 0; mi < 4; mi++)
#pragma unroll
        for (int nf = 0; nf < 4; nf++) {
            const float* d = acc[mi][nf];
            int c = wn * 32 + nf * 8 + cg;
            int r0 = wm * 64 + mi * 16 + rg;
            size_t o0 = (size_t)(p0 + r0) * DDIM + d0 + c;
            size_t o1 = o0 + (size_t)8 * DDIM;
            *(float2*)&g_Od[o0] = make_float2(d[0], d[1]);
            *(float2*)&g_Od[o1] = make_float2(d[2], d[3]);
        }
}

// ---------------- launch ----------------
extern "C" void kernel_launch(void* const* d_in, const int* in_sizes, int n_in,
                              void* d_out, int out_size) {
    const float* x      = (const float*)d_in[0];
    const float* w_gate = (const float*)d_in[1];
    const float* w_g    = (const float*)d_in[2];
    const float* w_u    = (const float*)d_in[3];
    const float* w_d    = (const float*)d_in[4];
    float* out = (float*)d_out;

    router_kernel<<<(T_TOKENS * 32 + 255) / 256, 256>>>(x, w_gate);
    scatter_kernel<<<(T_TOKENS + 255) / 256, 256>>>();
    gemm1_kernel<<<dim3(NTILES, MDIM / BN), 256>>>(x, w_g, w_u);
    gemm2_kernel<<<dim3(NTILES, DDIM / BN2), 256>>>(w_d);
    combine_kernel<<<(T_TOKENS * DDIM / 4 + 255) / 256, 256>>>((float4*)out);
}